// round 2
// baseline (speedup 1.0000x reference)
#include <cuda_runtime.h>
#include <cuda_bf16.h>

#define N_NODES 100000
#define IN_F 64
#define OUT_F 64

// Scratch for aggregated messages h = segment_sum(x[src], dst). 25.6 MB.
__device__ float g_h[(size_t)N_NODES * IN_F];

// ---------------------------------------------------------------------------
// Kernel 1: zero the h scratch (float4 stores)
// ---------------------------------------------------------------------------
__global__ void zero_h_kernel(int n4) {
    int i = blockIdx.x * blockDim.x + threadIdx.x;
    if (i < n4) {
        reinterpret_cast<float4*>(g_h)[i] = make_float4(0.f, 0.f, 0.f, 0.f);
    }
}

// ---------------------------------------------------------------------------
// Kernel 2: edge scatter. 16 threads per edge, each handles one float4 chunk
// of the 64-float row: h[dst[e]] += x[src[e]].
// x and g_h both fit in L2, so gathers/atomics are L2-resident.
// ---------------------------------------------------------------------------
__global__ void scatter_edges_kernel(const float4* __restrict__ x4,
                                     const int* __restrict__ src,
                                     const int* __restrict__ dst,
                                     int E) {
    int idx = blockIdx.x * blockDim.x + threadIdx.x;
    int e = idx >> 4;
    if (e >= E) return;
    int l = idx & 15;

    int s = __ldg(src + e);
    int d = __ldg(dst + e);

    float4 v = __ldg(x4 + (size_t)s * 16 + l);
    float* hp = g_h + (size_t)d * 64 + l * 4;
    atomicAdd(hp + 0, v.x);
    atomicAdd(hp + 1, v.y);
    atomicAdd(hp + 2, v.z);
    atomicAdd(hp + 3, v.w);
}

// ---------------------------------------------------------------------------
// Kernel 3: fused epilogue GEMM:
//   out[n][o] = sum_f h[n][f]*W_lin[o][f] + x[n][f]*W_self[o][f]
//             + b_lin[o] + b_self[o] + bias[o]
// Block: (64, 8) = 512 threads. Each thread owns one output feature o and
// 4 consecutive nodes -> 32 nodes per block. W cached transposed in smem so
// the per-f read sW[f*64+o] is conflict-free (consecutive o within a warp).
// ---------------------------------------------------------------------------
__global__ void __launch_bounds__(512)
out_gemm_kernel(const float* __restrict__ x,
                const float* __restrict__ W_lin,
                const float* __restrict__ b_lin,
                const float* __restrict__ W_self,
                const float* __restrict__ b_self,
                const float* __restrict__ bias,
                float* __restrict__ out,
                int N) {
    __shared__ float sWl[64 * 64];
    __shared__ float sWs[64 * 64];

    int tid = threadIdx.y * 64 + threadIdx.x;
    #pragma unroll
    for (int i = tid; i < 64 * 64; i += 512) {
        int o = i >> 6;
        int f = i & 63;
        sWl[f * 64 + o] = W_lin[i];   // store transposed
        sWs[f * 64 + o] = W_self[i];
    }
    __syncthreads();

    int o = threadIdx.x;
    float b = b_lin[o] + b_self[o] + bias[o];

    int n0 = blockIdx.x * 32 + threadIdx.y * 4;
    if (n0 >= N) return;
    bool full = (n0 + 3 < N);

    const float* __restrict__ hrow = g_h + (size_t)n0 * 64;
    const float* __restrict__ xrow = x + (size_t)n0 * 64;

    float acc0 = b, acc1 = b, acc2 = b, acc3 = b;

    if (full) {
        #pragma unroll 4
        for (int f = 0; f < 64; f++) {
            float wl = sWl[f * 64 + o];
            float ws = sWs[f * 64 + o];
            acc0 += hrow[f]       * wl + xrow[f]       * ws;
            acc1 += hrow[64 + f]  * wl + xrow[64 + f]  * ws;
            acc2 += hrow[128 + f] * wl + xrow[128 + f] * ws;
            acc3 += hrow[192 + f] * wl + xrow[192 + f] * ws;
        }
        float* op = out + (size_t)n0 * 64 + o;
        op[0]   = acc0;
        op[64]  = acc1;
        op[128] = acc2;
        op[192] = acc3;
    } else {
        // tail (not hit for N=100000, kept for safety)
        for (int j = 0; j < 4; j++) {
            int n = n0 + j;
            if (n >= N) break;
            float acc = b;
            for (int f = 0; f < 64; f++) {
                acc += g_h[(size_t)n * 64 + f] * sWl[f * 64 + o]
                     + x[(size_t)n * 64 + f]   * sWs[f * 64 + o];
            }
            out[(size_t)n * 64 + o] = acc;
        }
    }
}

// ---------------------------------------------------------------------------
// Launch. Input order per metadata: x, src, dst, W_lin, b_lin, W_self, b_self, bias
// ---------------------------------------------------------------------------
extern "C" void kernel_launch(void* const* d_in, const int* in_sizes, int n_in,
                              void* d_out, int out_size) {
    const float* x      = (const float*)d_in[0];
    const int*   src    = (const int*)d_in[1];
    const int*   dst    = (const int*)d_in[2];
    const float* W_lin  = (const float*)d_in[3];
    const float* b_lin  = (const float*)d_in[4];
    const float* W_self = (const float*)d_in[5];
    const float* b_self = (const float*)d_in[6];
    const float* bias   = (const float*)d_in[7];
    float* out = (float*)d_out;

    int N = in_sizes[0] / IN_F;   // 100000
    int E = in_sizes[1];          // 1280000

    // 1) zero h
    int n4 = N * (IN_F / 4);
    zero_h_kernel<<<(n4 + 255) / 256, 256>>>(n4);

    // 2) scatter edges (16 threads per edge)
    long long total = (long long)E * 16;
    int blocks = (int)((total + 255) / 256);
    scatter_edges_kernel<<<blocks, 256>>>((const float4*)x, src, dst, E);

    // 3) fused output GEMM
    dim3 blk(64, 8);
    int gblocks = (N + 31) / 32;
    out_gemm_kernel<<<gblocks, blk>>>(x, W_lin, b_lin, W_self, b_self, bias,
                                      out, N);
}

// round 3
// speedup vs baseline: 1.7444x; 1.7444x over previous
#include <cuda_runtime.h>
#include <cuda_bf16.h>

#define N_NODES 100000
#define IN_F 64
#define OUT_F 64

// Scratch for aggregated messages h = segment_sum(x[src], dst). 25.6 MB.
__device__ float g_h[(size_t)N_NODES * IN_F];

// ---------------------------------------------------------------------------
// Packed f32x2 FMA (Blackwell FFMA2 — only reachable via PTX)
// ---------------------------------------------------------------------------
__device__ __forceinline__ unsigned long long fma_f32x2(unsigned long long a,
                                                        unsigned long long b,
                                                        unsigned long long c) {
    unsigned long long d;
    asm("fma.rn.f32x2 %0, %1, %2, %3;" : "=l"(d) : "l"(a), "l"(b), "l"(c));
    return d;
}

__device__ __forceinline__ unsigned long long pack_f32x2(float lo, float hi) {
    unsigned long long r;
    asm("mov.b64 %0, {%1, %2};" : "=l"(r) : "f"(lo), "f"(hi));
    return r;
}

__device__ __forceinline__ float sum_f32x2(unsigned long long v) {
    float lo, hi;
    asm("mov.b64 {%0, %1}, %2;" : "=f"(lo), "=f"(hi) : "l"(v));
    return lo + hi;
}

// ---------------------------------------------------------------------------
// Kernel 1: zero the h scratch (float4 stores)
// ---------------------------------------------------------------------------
__global__ void zero_h_kernel(int n4) {
    int i = blockIdx.x * blockDim.x + threadIdx.x;
    if (i < n4) {
        reinterpret_cast<float4*>(g_h)[i] = make_float4(0.f, 0.f, 0.f, 0.f);
    }
}

// ---------------------------------------------------------------------------
// Kernel 2: edge scatter. 16 threads per edge, each handles one float4 chunk:
// h[dst[e]][16l..16l+3] += x[src[e]][...] via ONE red.global.add.v4.f32
// (4x fewer reduction lanes than scalar atomicAdd — REDG is lane-throughput
// bound on B300).
// ---------------------------------------------------------------------------
__global__ void scatter_edges_kernel(const float4* __restrict__ x4,
                                     const int* __restrict__ src,
                                     const int* __restrict__ dst,
                                     int E) {
    int idx = blockIdx.x * blockDim.x + threadIdx.x;
    int e = idx >> 4;
    if (e >= E) return;
    int l = idx & 15;

    int s = __ldg(src + e);   // uniform within the 16-thread group -> bcast
    int d = __ldg(dst + e);

    float4 v = __ldg(x4 + (size_t)s * 16 + l);
    float* hp = g_h + (size_t)d * 64 + l * 4;
    asm volatile("red.global.add.v4.f32 [%0], {%1, %2, %3, %4};"
                 :: "l"(hp), "f"(v.x), "f"(v.y), "f"(v.z), "f"(v.w)
                 : "memory");
}

// ---------------------------------------------------------------------------
// Kernel 3: fused epilogue GEMM with packed f32x2 FMAs:
//   out[n][o] = sum_f h[n][f]*W_lin[o][f] + x[n][f]*W_self[o][f] + b[o]
// Block (64,8)=512 threads; thread owns output feature o and 4 nodes.
// Weights cached in smem as [f4][o] float4 (transposed, 16B-aligned), read
// as ulonglong2 -> two packed f32x2 operands. h/x rows read as LDG.128
// (uniform across the warp's o-lanes -> broadcast).
// ---------------------------------------------------------------------------
__global__ void __launch_bounds__(512)
out_gemm_kernel(const float* __restrict__ x,
                const float* __restrict__ W_lin,
                const float* __restrict__ b_lin,
                const float* __restrict__ W_self,
                const float* __restrict__ b_self,
                const float* __restrict__ bias,
                float* __restrict__ out,
                int N) {
    __shared__ float sWl[64 * 64];   // layout: [f4][o][4]  (f4 = f/4)
    __shared__ float sWs[64 * 64];

    int tid = threadIdx.y * 64 + threadIdx.x;
    #pragma unroll
    for (int i = tid; i < 64 * 64; i += 512) {
        int o = i >> 6;
        int f = i & 63;
        int dsti = (f >> 2) * 256 + o * 4 + (f & 3);
        sWl[dsti] = W_lin[i];
        sWs[dsti] = W_self[i];
    }
    __syncthreads();

    int o = threadIdx.x;
    float b = b_lin[o] + b_self[o] + bias[o];

    int n0 = blockIdx.x * 32 + threadIdx.y * 4;
    if (n0 >= N) return;
    bool full = (n0 + 3 < N);

    const float* __restrict__ hrow = g_h + (size_t)n0 * 64;
    const float* __restrict__ xrow = x + (size_t)n0 * 64;

    if (full) {
        unsigned long long acc0 = pack_f32x2(b, 0.f);
        unsigned long long acc1 = acc0, acc2 = acc0, acc3 = acc0;

        #pragma unroll
        for (int f4 = 0; f4 < 16; f4++) {
            // weights: float4 viewed as 2 packed f32x2 (LDS.128)
            ulonglong2 wl = *reinterpret_cast<const ulonglong2*>(
                                &sWl[f4 * 256 + o * 4]);
            ulonglong2 ws = *reinterpret_cast<const ulonglong2*>(
                                &sWs[f4 * 256 + o * 4]);

            ulonglong2 h0 = *reinterpret_cast<const ulonglong2*>(hrow + f4 * 4);
            ulonglong2 h1 = *reinterpret_cast<const ulonglong2*>(hrow + 64 + f4 * 4);
            ulonglong2 h2 = *reinterpret_cast<const ulonglong2*>(hrow + 128 + f4 * 4);
            ulonglong2 h3 = *reinterpret_cast<const ulonglong2*>(hrow + 192 + f4 * 4);
            ulonglong2 x0 = *reinterpret_cast<const ulonglong2*>(xrow + f4 * 4);
            ulonglong2 x1 = *reinterpret_cast<const ulonglong2*>(xrow + 64 + f4 * 4);
            ulonglong2 x2 = *reinterpret_cast<const ulonglong2*>(xrow + 128 + f4 * 4);
            ulonglong2 x3 = *reinterpret_cast<const ulonglong2*>(xrow + 192 + f4 * 4);

            acc0 = fma_f32x2(h0.x, wl.x, acc0);
            acc0 = fma_f32x2(h0.y, wl.y, acc0);
            acc0 = fma_f32x2(x0.x, ws.x, acc0);
            acc0 = fma_f32x2(x0.y, ws.y, acc0);

            acc1 = fma_f32x2(h1.x, wl.x, acc1);
            acc1 = fma_f32x2(h1.y, wl.y, acc1);
            acc1 = fma_f32x2(x1.x, ws.x, acc1);
            acc1 = fma_f32x2(x1.y, ws.y, acc1);

            acc2 = fma_f32x2(h2.x, wl.x, acc2);
            acc2 = fma_f32x2(h2.y, wl.y, acc2);
            acc2 = fma_f32x2(x2.x, ws.x, acc2);
            acc2 = fma_f32x2(x2.y, ws.y, acc2);

            acc3 = fma_f32x2(h3.x, wl.x, acc3);
            acc3 = fma_f32x2(h3.y, wl.y, acc3);
            acc3 = fma_f32x2(x3.x, ws.x, acc3);
            acc3 = fma_f32x2(x3.y, ws.y, acc3);
        }

        float* op = out + (size_t)n0 * 64 + o;
        op[0]   = sum_f32x2(acc0);
        op[64]  = sum_f32x2(acc1);
        op[128] = sum_f32x2(acc2);
        op[192] = sum_f32x2(acc3);
    } else {
        // tail (not hit for N=100000, kept for safety)
        for (int j = 0; j < 4; j++) {
            int n = n0 + j;
            if (n >= N) break;
            float acc = b;
            for (int f = 0; f < 64; f++) {
                acc += g_h[(size_t)n * 64 + f] * sWl[(f >> 2) * 256 + o * 4 + (f & 3)]
                     + x[(size_t)n * 64 + f]   * sWs[(f >> 2) * 256 + o * 4 + (f & 3)];
            }
            out[(size_t)n * 64 + o] = acc;
        }
    }
}

// ---------------------------------------------------------------------------
// Launch. Input order per metadata: x, src, dst, W_lin, b_lin, W_self, b_self, bias
// ---------------------------------------------------------------------------
extern "C" void kernel_launch(void* const* d_in, const int* in_sizes, int n_in,
                              void* d_out, int out_size) {
    const float* x      = (const float*)d_in[0];
    const int*   src    = (const int*)d_in[1];
    const int*   dst    = (const int*)d_in[2];
    const float* W_lin  = (const float*)d_in[3];
    const float* b_lin  = (const float*)d_in[4];
    const float* W_self = (const float*)d_in[5];
    const float* b_self = (const float*)d_in[6];
    const float* bias   = (const float*)d_in[7];
    float* out = (float*)d_out;

    int N = in_sizes[0] / IN_F;   // 100000
    int E = in_sizes[1];          // 1280000

    // 1) zero h
    int n4 = N * (IN_F / 4);
    zero_h_kernel<<<(n4 + 255) / 256, 256>>>(n4);

    // 2) scatter edges (16 threads per edge, one red.v4 each)
    long long total = (long long)E * 16;
    int blocks = (int)((total + 255) / 256);
    scatter_edges_kernel<<<blocks, 256>>>((const float4*)x, src, dst, E);

    // 3) fused output GEMM
    dim3 blk(64, 8);
    int gblocks = (N + 31) / 32;
    out_gemm_kernel<<<gblocks, blk>>>(x, W_lin, b_lin, W_self, b_self, bias,
                                      out, N);
}

// round 4
// speedup vs baseline: 2.2111x; 1.2675x over previous
#include <cuda_runtime.h>
#include <cuda_bf16.h>

#define N_NODES 100000
#define IN_F 64
#define OUT_F 64
#define E_MAX 1600000
#define SCAN_BS 1024

// CSR scratch
__device__ int g_deg[N_NODES];        // per-node in-degree
__device__ int g_off[N_NODES];        // CSR start offsets
__device__ int g_cursor[N_NODES];     // fill cursors
__device__ int g_eidx[E_MAX];         // src node per edge, bucketed by dst
__device__ int g_blocksums[128];      // scan partials (ceil(100000/1024)=98)

// ---------------------------------------------------------------------------
// Packed f32x2 FMA (Blackwell FFMA2 — only reachable via PTX)
// ---------------------------------------------------------------------------
__device__ __forceinline__ unsigned long long fma_f32x2(unsigned long long a,
                                                        unsigned long long b,
                                                        unsigned long long c) {
    unsigned long long d;
    asm("fma.rn.f32x2 %0, %1, %2, %3;" : "=l"(d) : "l"(a), "l"(b), "l"(c));
    return d;
}
__device__ __forceinline__ unsigned long long pack_f32x2(float lo, float hi) {
    unsigned long long r;
    asm("mov.b64 %0, {%1, %2};" : "=l"(r) : "f"(lo), "f"(hi));
    return r;
}
__device__ __forceinline__ float sum_f32x2(unsigned long long v) {
    float lo, hi;
    asm("mov.b64 {%0, %1}, %2;" : "=f"(lo), "=f"(hi) : "l"(v));
    return lo + hi;
}

// ---------------------------------------------------------------------------
// CSR build kernels
// ---------------------------------------------------------------------------
__global__ void zero_deg_kernel(int n) {
    int i = blockIdx.x * blockDim.x + threadIdx.x;
    if (i < n) g_deg[i] = 0;
}

__global__ void count_deg_kernel(const int* __restrict__ dst, int E) {
    int e = blockIdx.x * blockDim.x + threadIdx.x;
    if (e < E) atomicAdd(&g_deg[dst[e]], 1);
}

// Per-1024-block inclusive scan of g_deg; writes exclusive-within-block to
// g_off and block total to g_blocksums.
__global__ void __launch_bounds__(SCAN_BS) scan_phase1(int n) {
    __shared__ int buf0[SCAN_BS];
    __shared__ int buf1[SCAN_BS];
    int t = threadIdx.x;
    int i = blockIdx.x * SCAN_BS + t;
    int v = (i < n) ? g_deg[i] : 0;
    buf0[t] = v;
    __syncthreads();
    int* in = buf0;
    int* out = buf1;
    #pragma unroll
    for (int off = 1; off < SCAN_BS; off <<= 1) {
        int s = in[t];
        if (t >= off) s += in[t - off];
        out[t] = s;
        __syncthreads();
        int* tmp = in; in = out; out = tmp;
    }
    if (t == SCAN_BS - 1) g_blocksums[blockIdx.x] = in[t];
    if (i < n) g_off[i] = in[t] - v;   // exclusive within block
}

// Single-block exclusive scan of g_blocksums (nb <= 128).
__global__ void __launch_bounds__(128) scan_phase2(int nb) {
    __shared__ int buf0[128];
    __shared__ int buf1[128];
    int t = threadIdx.x;
    int v = (t < nb) ? g_blocksums[t] : 0;
    buf0[t] = v;
    __syncthreads();
    int* in = buf0;
    int* out = buf1;
    #pragma unroll
    for (int off = 1; off < 128; off <<= 1) {
        int s = in[t];
        if (t >= off) s += in[t - off];
        out[t] = s;
        __syncthreads();
        int* tmp = in; in = out; out = tmp;
    }
    if (t < nb) g_blocksums[t] = in[t] - v;  // exclusive
}

// Add block base; init cursor.
__global__ void scan_phase3(int n) {
    int i = blockIdx.x * SCAN_BS + threadIdx.x;
    if (i < n) {
        int s = g_off[i] + g_blocksums[blockIdx.x];
        g_off[i] = s;
        g_cursor[i] = s;
    }
}

__global__ void fill_buckets_kernel(const int* __restrict__ src,
                                    const int* __restrict__ dst, int E) {
    int e = blockIdx.x * blockDim.x + threadIdx.x;
    if (e < E) {
        int pos = atomicAdd(&g_cursor[dst[e]], 1);
        g_eidx[pos] = src[e];
    }
}

// ---------------------------------------------------------------------------
// Fused kernel: per block, aggregate h rows for 32 nodes into smem (gather
// over CSR, no atomics), then epilogue GEMM with packed f32x2 FMAs:
//   out[n][o] = sum_f h[n][f]*W_lin[o][f] + x[n][f]*W_self[o][f] + b[o]
// ---------------------------------------------------------------------------
__global__ void __launch_bounds__(512)
fused_agg_gemm_kernel(const float* __restrict__ x,
                      const float* __restrict__ W_lin,
                      const float* __restrict__ b_lin,
                      const float* __restrict__ W_self,
                      const float* __restrict__ b_self,
                      const float* __restrict__ bias,
                      float* __restrict__ out,
                      int N) {
    __shared__ float sWl[64 * 64];       // layout: [f4][o][4]
    __shared__ float sWs[64 * 64];
    __shared__ float4 sh4[32 * 16];      // h tile: 32 nodes x 64 floats (8KB)

    const float4* __restrict__ x4 = (const float4*)x;
    int tid = threadIdx.x;

    // Load weights transposed into smem.
    #pragma unroll
    for (int i = tid; i < 64 * 64; i += 512) {
        int o = i >> 6;
        int f = i & 63;
        int dsti = (f >> 2) * 256 + o * 4 + (f & 3);
        sWl[dsti] = W_lin[i];
        sWs[dsti] = W_self[i];
    }

    // ---- Phase 1: gather-aggregate h rows (16 threads per node) ----
    int nl = tid >> 4;          // 0..31 local node
    int l  = tid & 15;          // float4 chunk within row
    int node = blockIdx.x * 32 + nl;

    float4 acc = make_float4(0.f, 0.f, 0.f, 0.f);
    if (node < N) {
        int beg = g_off[node];
        int cnt = g_deg[node];
        for (int j = 0; j < cnt; j++) {
            int s = __ldg(g_eidx + beg + j);   // same addr across 16 lanes
            float4 v = __ldg(x4 + (size_t)s * 16 + l);
            acc.x += v.x; acc.y += v.y; acc.z += v.z; acc.w += v.w;
        }
    }
    sh4[nl * 16 + l] = acc;
    __syncthreads();

    // ---- Phase 2: GEMM epilogue ----
    int o  = tid & 63;
    int yg = tid >> 6;              // 0..7
    int n0l = yg * 4;               // local node group of 4
    int n0 = blockIdx.x * 32 + n0l;
    if (n0 >= N) return;
    bool full = (n0 + 3 < N);

    float b = b_lin[o] + b_self[o] + bias[o];
    const float* __restrict__ hrow = (const float*)sh4 + n0l * 64;
    const float* __restrict__ xrow = x + (size_t)n0 * 64;

    if (full) {
        unsigned long long acc0 = pack_f32x2(b, 0.f);
        unsigned long long acc1 = acc0, acc2 = acc0, acc3 = acc0;

        #pragma unroll
        for (int f4 = 0; f4 < 16; f4++) {
            ulonglong2 wl = *reinterpret_cast<const ulonglong2*>(
                                &sWl[f4 * 256 + o * 4]);
            ulonglong2 ws = *reinterpret_cast<const ulonglong2*>(
                                &sWs[f4 * 256 + o * 4]);

            ulonglong2 h0 = *reinterpret_cast<const ulonglong2*>(hrow + f4 * 4);
            ulonglong2 h1 = *reinterpret_cast<const ulonglong2*>(hrow + 64 + f4 * 4);
            ulonglong2 h2 = *reinterpret_cast<const ulonglong2*>(hrow + 128 + f4 * 4);
            ulonglong2 h3 = *reinterpret_cast<const ulonglong2*>(hrow + 192 + f4 * 4);
            ulonglong2 x0 = *reinterpret_cast<const ulonglong2*>(xrow + f4 * 4);
            ulonglong2 x1 = *reinterpret_cast<const ulonglong2*>(xrow + 64 + f4 * 4);
            ulonglong2 x2 = *reinterpret_cast<const ulonglong2*>(xrow + 128 + f4 * 4);
            ulonglong2 x3 = *reinterpret_cast<const ulonglong2*>(xrow + 192 + f4 * 4);

            acc0 = fma_f32x2(h0.x, wl.x, acc0);
            acc0 = fma_f32x2(h0.y, wl.y, acc0);
            acc0 = fma_f32x2(x0.x, ws.x, acc0);
            acc0 = fma_f32x2(x0.y, ws.y, acc0);

            acc1 = fma_f32x2(h1.x, wl.x, acc1);
            acc1 = fma_f32x2(h1.y, wl.y, acc1);
            acc1 = fma_f32x2(x1.x, ws.x, acc1);
            acc1 = fma_f32x2(x1.y, ws.y, acc1);

            acc2 = fma_f32x2(h2.x, wl.x, acc2);
            acc2 = fma_f32x2(h2.y, wl.y, acc2);
            acc2 = fma_f32x2(x2.x, ws.x, acc2);
            acc2 = fma_f32x2(x2.y, ws.y, acc2);

            acc3 = fma_f32x2(h3.x, wl.x, acc3);
            acc3 = fma_f32x2(h3.y, wl.y, acc3);
            acc3 = fma_f32x2(x3.x, ws.x, acc3);
            acc3 = fma_f32x2(x3.y, ws.y, acc3);
        }

        float* op = out + (size_t)n0 * 64 + o;
        op[0]   = sum_f32x2(acc0);
        op[64]  = sum_f32x2(acc1);
        op[128] = sum_f32x2(acc2);
        op[192] = sum_f32x2(acc3);
    } else {
        for (int j = 0; j < 4; j++) {
            int n = n0 + j;
            if (n >= N) break;
            float a = b;
            const float* hr = (const float*)sh4 + (n0l + j) * 64;
            for (int f = 0; f < 64; f++) {
                a += hr[f] * sWl[(f >> 2) * 256 + o * 4 + (f & 3)]
                   + x[(size_t)n * 64 + f] * sWs[(f >> 2) * 256 + o * 4 + (f & 3)];
            }
            out[(size_t)n * 64 + o] = a;
        }
    }
}

// ---------------------------------------------------------------------------
// Launch. Input order per metadata: x, src, dst, W_lin, b_lin, W_self, b_self, bias
// ---------------------------------------------------------------------------
extern "C" void kernel_launch(void* const* d_in, const int* in_sizes, int n_in,
                              void* d_out, int out_size) {
    const float* x      = (const float*)d_in[0];
    const int*   src    = (const int*)d_in[1];
    const int*   dst    = (const int*)d_in[2];
    const float* W_lin  = (const float*)d_in[3];
    const float* b_lin  = (const float*)d_in[4];
    const float* W_self = (const float*)d_in[5];
    const float* b_self = (const float*)d_in[6];
    const float* bias   = (const float*)d_in[7];
    float* out = (float*)d_out;

    int N = in_sizes[0] / IN_F;   // 100000
    int E = in_sizes[1];          // 1280000

    int nb = (N + SCAN_BS - 1) / SCAN_BS;   // 98

    // CSR build
    zero_deg_kernel<<<(N + 255) / 256, 256>>>(N);
    count_deg_kernel<<<(E + 255) / 256, 256>>>(dst, E);
    scan_phase1<<<nb, SCAN_BS>>>(N);
    scan_phase2<<<1, 128>>>(nb);
    scan_phase3<<<nb, SCAN_BS>>>(N);
    fill_buckets_kernel<<<(E + 255) / 256, 256>>>(src, dst, E);

    // Fused aggregate + GEMM
    int gblocks = (N + 31) / 32;
    fused_agg_gemm_kernel<<<gblocks, 512>>>(x, W_lin, b_lin, W_self, b_self,
                                            bias, out, N);
}